// round 16
// baseline (speedup 1.0000x reference)
#include <cuda_runtime.h>
#include <cuda_fp16.h>

// DNM_Linear: out[b,o] = relu(0.25 * sum_{m,i} relu(x[b,i]*W[o,m,i] - q[o,m,i]) - 0.05)
// x: [512,512] f32; W,q: [128,8,512] -> flat [1024,512] f32; out: [512,128] f32
//
// fp16 mainloop (HFMA2/HMAX2/HADD2), f32 flush per KC=64 chunk with fp16 g-tree.
// 512 thr/CTA, tile 64x64, warp = 16 tx (2 rows) x 2 ty (k parity),
// wid=(cg,rg): cg -> one m-group of 8 neuron cols (broadcast w/q), rg -> row half.
// Explicit register double-buffer of smem operands (macro m+1 overlaps macro m).

#define IN_DIM   512
#define OUT_DIM  128
#define NEUR     1024
#define B_TOT    512
#define KC       64
#define NMAC     16              // macro steps per chunk (2 kk each)
#define PITCH2   68              // half2 per kk-row (64 entities + 4 pad)
#define NKK      32              // kk rows per chunk
#define ARR2     (NKK*PITCH2)    // 2176 half2 per array
#define BUF2     (3*ARR2)        // x, w, -q
#define SMEM_BYTES (2*BUF2*4)    // 52224 B

typedef unsigned long long u64;

extern __shared__ __half2 smh[];

__device__ __forceinline__ void stage(__half2* base, int kk0, int e,
                                      const float4 px[2], const float4 pw[2], const float4 pq[2])
{
#pragma unroll
    for (int h = 0; h < 2; h++) {
        const int kk = kk0 + h * 16;
        base[(kk    ) * PITCH2 + e]            = __floats2half2_rn(px[h].x, px[h].y);
        base[(kk + 1) * PITCH2 + e]            = __floats2half2_rn(px[h].z, px[h].w);
        base[ARR2 + (kk    ) * PITCH2 + e]     = __floats2half2_rn(pw[h].x, pw[h].y);
        base[ARR2 + (kk + 1) * PITCH2 + e]     = __floats2half2_rn(pw[h].z, pw[h].w);
        base[2*ARR2 + (kk    ) * PITCH2 + e]   = __floats2half2_rn(-pq[h].x, -pq[h].y);
        base[2*ARR2 + (kk + 1) * PITCH2 + e]   = __floats2half2_rn(-pq[h].z, -pq[h].w);
    }
}

__global__ __launch_bounds__(512, 1)
void dnm_kernel(const float* __restrict__ x,
                const float* __restrict__ W,
                const float* __restrict__ q,
                float* __restrict__ out)
{
    const int t    = threadIdx.x;
    const int lane = t & 31;
    const int wid  = t >> 5;
    const int tx   = lane & 15;
    const int ty   = lane >> 4;       // kk parity within macro step
    const int cg   = wid & 7;         // neuron cols cg*8 .. cg*8+7 (one m-group)
    const int rg   = wid >> 3;        // batch rows rg*32 + tx*2 + {0,1}
    const int n0   = blockIdx.x * 64;
    const int b0   = blockIdx.y * 64;

    // global load mapping: 8 threads per entity row, float4 at kq and kq+32
    const int e  = t >> 3;
    const int kq = (t & 7) * 4;
    const float* xg = x + (size_t)(b0 + e) * IN_DIM + kq;
    const float* wg = W + (size_t)(n0 + e) * IN_DIM + kq;
    const float* qg = q + (size_t)(n0 + e) * IN_DIM + kq;
    const int kk0 = kq >> 1;          // 0..14 even

    // f32 totals: rows {0,1} x 2 g-tree halves (half2 lane pair kept)
    float2 facc[2][2];
#pragma unroll
    for (int r = 0; r < 2; r++)
#pragma unroll
        for (int h = 0; h < 2; h++) facc[r][h] = make_float2(0.f, 0.f);

    const __half2 hzero = __float2half2_rn(0.f);

    float4 px[2], pw[2], pq[2];

    // ---- prologue: load + stage chunk 0
#pragma unroll
    for (int h = 0; h < 2; h++) {
        px[h] = *(const float4*)(xg + h * 32);
        pw[h] = *(const float4*)(wg + h * 32);
        pq[h] = *(const float4*)(qg + h * 32);
    }
    stage(smh, kk0, e, px, pw, pq);
    __syncthreads();

    const int NCHUNK = IN_DIM / KC;   // 8

    for (int c = 0; c < NCHUNK; c++) {
        // global prefetch for chunk c+1 (staged mid-loop below)
        if (c < NCHUNK - 1) {
            const int kn = (c + 1) * KC;
#pragma unroll
            for (int h = 0; h < 2; h++) {
                px[h] = *(const float4*)(xg + kn + h * 32);
                pw[h] = *(const float4*)(wg + kn + h * 32);
                pq[h] = *(const float4*)(qg + kn + h * 32);
            }
        }

        const __half2* cb  = smh + (c & 1) * BUF2;
        const __half2* bxp = cb + rg * 32 + tx * 2;
        const __half2* bwp = cb + ARR2 + cg * 8;
        const __half2* bqp = cb + 2 * ARR2 + cg * 8;

        // fp16 chunk accumulators
        __half2 hacc[2][8];
#pragma unroll
        for (int r = 0; r < 2; r++)
#pragma unroll
            for (int g = 0; g < 8; g++) hacc[r][g] = hzero;

        // explicit register double-buffer of operands
        u64  xv[2];
        uint4 wa[2], wb[2], qa[2], qb[2];

        // load macro 0
        {
            const int off0 = ty * PITCH2;
            xv[0] = *reinterpret_cast<const u64*>(bxp + off0);
            wa[0] = *reinterpret_cast<const uint4*>(bwp + off0);
            wb[0] = *reinterpret_cast<const uint4*>(bwp + off0 + 4);
            qa[0] = *reinterpret_cast<const uint4*>(bqp + off0);
            qb[0] = *reinterpret_cast<const uint4*>(bqp + off0 + 4);
        }

#pragma unroll
        for (int m = 0; m < NMAC; m++) {
            const int cur = m & 1;
            const int nxt = cur ^ 1;

            // prefetch macro m+1 operands (overlaps math below)
            if (m < NMAC - 1) {
                const int off = (2 * (m + 1) + ty) * PITCH2;
                xv[nxt] = *reinterpret_cast<const u64*>(bxp + off);
                wa[nxt] = *reinterpret_cast<const uint4*>(bwp + off);
                wb[nxt] = *reinterpret_cast<const uint4*>(bwp + off + 4);
                qa[nxt] = *reinterpret_cast<const uint4*>(bqp + off);
                qb[nxt] = *reinterpret_cast<const uint4*>(bqp + off + 4);
            }

            // mid-loop: stage prefetched globals into the other smem buffer
            if (m == 8 && c < NCHUNK - 1) {
                stage(smh + ((c + 1) & 1) * BUF2, kk0, e, px, pw, pq);
            }

            const __half2* hx  = reinterpret_cast<const __half2*>(&xv[cur]);
            const __half2* hw0 = reinterpret_cast<const __half2*>(&wa[cur]);
            const __half2* hw1 = reinterpret_cast<const __half2*>(&wb[cur]);
            const __half2* hq0 = reinterpret_cast<const __half2*>(&qa[cur]);
            const __half2* hq1 = reinterpret_cast<const __half2*>(&qb[cur]);

#pragma unroll
            for (int r = 0; r < 2; r++) {
#pragma unroll
                for (int g = 0; g < 4; g++) {
                    hacc[r][g]     = __hadd2(hacc[r][g],
                                      __hmax2(__hfma2(hx[r], hw0[g], hq0[g]), hzero));
                    hacc[r][g + 4] = __hadd2(hacc[r][g + 4],
                                      __hmax2(__hfma2(hx[r], hw1[g], hq1[g]), hzero));
                }
            }
        }

        // ---- flush: fp16 tree over g (8 -> 4 -> 2), then f32 accumulate
#pragma unroll
        for (int r = 0; r < 2; r++) {
            __half2 s0 = __hadd2(__hadd2(hacc[r][0], hacc[r][1]),
                                 __hadd2(hacc[r][2], hacc[r][3]));
            __half2 s1 = __hadd2(__hadd2(hacc[r][4], hacc[r][5]),
                                 __hadd2(hacc[r][6], hacc[r][7]));
            float2 f0 = __half22float2(s0);
            float2 f1 = __half22float2(s1);
            facc[r][0].x += f0.x;  facc[r][0].y += f0.y;
            facc[r][1].x += f1.x;  facc[r][1].y += f1.y;
        }

        __syncthreads();
    }

    // ---- epilogue: in-thread sum, fold k-parity (xor16)
    const unsigned FULL = 0xffffffffu;
#pragma unroll
    for (int r = 0; r < 2; r++) {
        float s = facc[r][0].x + facc[r][0].y + facc[r][1].x + facc[r][1].y;

        s += __shfl_xor_sync(FULL, s, 16);      // fold k parity (ty)

        if (ty == 0) {
            const int b = b0 + rg * 32 + tx * 2 + r;
            const int o = (n0 >> 3) + cg;
            out[b * OUT_DIM + o] = fmaxf(0.25f * s - 0.05f, 0.f);
        }
    }
}

extern "C" void kernel_launch(void* const* d_in, const int* in_sizes, int n_in,
                              void* d_out, int out_size)
{
    const float* x = (const float*)d_in[0];
    const float* W = (const float*)d_in[1];
    const float* q = (const float*)d_in[2];
    float* out = (float*)d_out;

    cudaFuncSetAttribute(dnm_kernel, cudaFuncAttributeMaxDynamicSharedMemorySize, SMEM_BYTES);

    dim3 grid(NEUR / 64, B_TOT / 64);   // 128 CTAs, 512 threads
    dnm_kernel<<<grid, 512, SMEM_BYTES>>>(x, W, q, out);
}

// round 17
// speedup vs baseline: 1.0982x; 1.0982x over previous
#include <cuda_runtime.h>
#include <cuda_fp16.h>

// DNM_Linear: out[b,o] = relu(0.25 * sum_{m,i} relu(x[b,i]*W[o,m,i] - q[o,m,i]) - 0.05)
// x: [512,512] f32; W,q: [128,8,512] -> flat [1024,512] f32; out: [512,128] f32
//
// fp16 mainloop (HFMA2/HMAX2/HADD2) with f32 flush per KC=128 chunk.
// 512 thr/CTA, tile 64x64, warp = 16 tx (2 rows) x 2 ty (k parity),
// wid=(cg,rg): cg -> one m-group of 8 neuron cols (broadcast w/q), rg -> row half.
// Two-phase staging keeps prefetch register cost at the KC=64 level.

#define IN_DIM   512
#define OUT_DIM  128
#define NEUR     1024
#define B_TOT    512
#define KC       128
#define NMAC     32              // macro steps per chunk (2 kk each)
#define PITCH2   68              // half2 per kk-row (64 entities + 4 pad)
#define NKK      64              // kk rows per chunk
#define ARR2     (NKK*PITCH2)    // 4352 half2 per array
#define BUF2     (3*ARR2)        // x, w, -q
#define SMEM_BYTES (2*BUF2*4)    // 104448 B

typedef unsigned long long u64;

extern __shared__ __half2 smh[];

// stage one 64-k half (h-loop covers 2x16 kk rows) at kk base half*32
__device__ __forceinline__ void stage(__half2* base, int kk0, int e, int half,
                                      const float4 px[2], const float4 pw[2], const float4 pq[2])
{
#pragma unroll
    for (int h = 0; h < 2; h++) {
        const int kk = half * 32 + kk0 + h * 16;
        base[(kk    ) * PITCH2 + e]            = __floats2half2_rn(px[h].x, px[h].y);
        base[(kk + 1) * PITCH2 + e]            = __floats2half2_rn(px[h].z, px[h].w);
        base[ARR2 + (kk    ) * PITCH2 + e]     = __floats2half2_rn(pw[h].x, pw[h].y);
        base[ARR2 + (kk + 1) * PITCH2 + e]     = __floats2half2_rn(pw[h].z, pw[h].w);
        base[2*ARR2 + (kk    ) * PITCH2 + e]   = __floats2half2_rn(-pq[h].x, -pq[h].y);
        base[2*ARR2 + (kk + 1) * PITCH2 + e]   = __floats2half2_rn(-pq[h].z, -pq[h].w);
    }
}

__global__ __launch_bounds__(512, 1)
void dnm_kernel(const float* __restrict__ x,
                const float* __restrict__ W,
                const float* __restrict__ q,
                float* __restrict__ out)
{
    const int t    = threadIdx.x;
    const int lane = t & 31;
    const int wid  = t >> 5;
    const int tx   = lane & 15;
    const int ty   = lane >> 4;       // kk parity within macro step
    const int cg   = wid & 7;         // neuron cols cg*8 .. cg*8+7 (one m-group)
    const int rg   = wid >> 3;        // batch rows rg*32 + tx*2 + {0,1}
    const int n0   = blockIdx.x * 64;
    const int b0   = blockIdx.y * 64;

    // global load mapping: 8 threads per entity row, float4 at kq and kq+32 (per 64-k half)
    const int e  = t >> 3;
    const int kq = (t & 7) * 4;
    const float* xg = x + (size_t)(b0 + e) * IN_DIM + kq;
    const float* wg = W + (size_t)(n0 + e) * IN_DIM + kq;
    const float* qg = q + (size_t)(n0 + e) * IN_DIM + kq;
    const int kk0 = kq >> 1;          // 0..14 even

    // f32 totals: rows {0,1} x 8 cols
    float2 facc[2][8];
#pragma unroll
    for (int r = 0; r < 2; r++)
#pragma unroll
        for (int g = 0; g < 8; g++) facc[r][g] = make_float2(0.f, 0.f);

    const __half2 hzero = __float2half2_rn(0.f);

    float4 px[2], pw[2], pq[2];

    // ---- prologue: load + stage both halves of chunk 0
#pragma unroll
    for (int half = 0; half < 2; half++) {
        const int kb = half * 64;
#pragma unroll
        for (int h = 0; h < 2; h++) {
            px[h] = *(const float4*)(xg + kb + h * 32);
            pw[h] = *(const float4*)(wg + kb + h * 32);
            pq[h] = *(const float4*)(qg + kb + h * 32);
        }
        stage(smh, kk0, e, half, px, pw, pq);
    }
    __syncthreads();

    const int NCHUNK = IN_DIM / KC;   // 4

    for (int c = 0; c < NCHUNK; c++) {
        // phase-A global prefetch for chunk c+1 (half 0), staged at m==8
        if (c < NCHUNK - 1) {
            const int kn = (c + 1) * KC;
#pragma unroll
            for (int h = 0; h < 2; h++) {
                px[h] = *(const float4*)(xg + kn + h * 32);
                pw[h] = *(const float4*)(wg + kn + h * 32);
                pq[h] = *(const float4*)(qg + kn + h * 32);
            }
        }

        const __half2* cb  = smh + (c & 1) * BUF2;
        const __half2* bxp = cb + rg * 32 + tx * 2;
        const __half2* bwp = cb + ARR2 + cg * 8;
        const __half2* bqp = cb + 2 * ARR2 + cg * 8;

        // fp16 chunk accumulators (<= 64 elems per half-lane chain)
        __half2 hacc[2][8];
#pragma unroll
        for (int r = 0; r < 2; r++)
#pragma unroll
            for (int g = 0; g < 8; g++) hacc[r][g] = hzero;

#pragma unroll
        for (int m = 0; m < NMAC; m++) {
            const int off = (2 * m + ty) * PITCH2;

            u64 xv   = *reinterpret_cast<const u64*>(bxp + off);        // rows tx*2, tx*2+1
            uint4 wa = *reinterpret_cast<const uint4*>(bwp + off);      // cols 0-3
            uint4 wb = *reinterpret_cast<const uint4*>(bwp + off + 4);  // cols 4-7
            uint4 qa = *reinterpret_cast<const uint4*>(bqp + off);
            uint4 qb = *reinterpret_cast<const uint4*>(bqp + off + 4);

            if (c < NCHUNK - 1) {
                // stage phase-A (half 0) into the other buffer
                if (m == 8)
                    stage(smh + ((c + 1) & 1) * BUF2, kk0, e, 0, px, pw, pq);
                // phase-B global prefetch (half 1)
                if (m == 10) {
                    const int kn = (c + 1) * KC + 64;
#pragma unroll
                    for (int h = 0; h < 2; h++) {
                        px[h] = *(const float4*)(xg + kn + h * 32);
                        pw[h] = *(const float4*)(wg + kn + h * 32);
                        pq[h] = *(const float4*)(qg + kn + h * 32);
                    }
                }
                // stage phase-B (half 1)
                if (m == 20)
                    stage(smh + ((c + 1) & 1) * BUF2, kk0, e, 1, px, pw, pq);
            }

            const __half2* hx  = reinterpret_cast<const __half2*>(&xv);
            const __half2* hw0 = reinterpret_cast<const __half2*>(&wa);
            const __half2* hw1 = reinterpret_cast<const __half2*>(&wb);
            const __half2* hq0 = reinterpret_cast<const __half2*>(&qa);
            const __half2* hq1 = reinterpret_cast<const __half2*>(&qb);

#pragma unroll
            for (int r = 0; r < 2; r++) {
#pragma unroll
                for (int g = 0; g < 4; g++) {
                    hacc[r][g]     = __hadd2(hacc[r][g],
                                      __hmax2(__hfma2(hx[r], hw0[g], hq0[g]), hzero));
                    hacc[r][g + 4] = __hadd2(hacc[r][g + 4],
                                      __hmax2(__hfma2(hx[r], hw1[g], hq1[g]), hzero));
                }
            }
        }

        // ---- flush fp16 chunk partials into f32 totals
#pragma unroll
        for (int r = 0; r < 2; r++)
#pragma unroll
            for (int g = 0; g < 8; g++) {
                float2 f = __half22float2(hacc[r][g]);
                facc[r][g].x += f.x;
                facc[r][g].y += f.y;
            }

        __syncthreads();
    }

    // ---- epilogue: in-thread sum over 8 cols (one m-group), fold k-parity (xor16)
    const unsigned FULL = 0xffffffffu;
#pragma unroll
    for (int r = 0; r < 2; r++) {
        float s = 0.f;
#pragma unroll
        for (int g = 0; g < 8; g++)
            s += facc[r][g].x + facc[r][g].y;

        s += __shfl_xor_sync(FULL, s, 16);      // fold k parity (ty)

        if (ty == 0) {
            const int b = b0 + rg * 32 + tx * 2 + r;
            const int o = (n0 >> 3) + cg;
            out[b * OUT_DIM + o] = fmaxf(0.25f * s - 0.05f, 0.f);
        }
    }
}

extern "C" void kernel_launch(void* const* d_in, const int* in_sizes, int n_in,
                              void* d_out, int out_size)
{
    const float* x = (const float*)d_in[0];
    const float* W = (const float*)d_in[1];
    const float* q = (const float*)d_in[2];
    float* out = (float*)d_out;

    cudaFuncSetAttribute(dnm_kernel, cudaFuncAttributeMaxDynamicSharedMemorySize, SMEM_BYTES);

    dim3 grid(NEUR / 64, B_TOT / 64);   // 128 CTAs, 512 threads
    dnm_kernel<<<grid, 512, SMEM_BYTES>>>(x, W, q, out);
}